// round 2
// baseline (speedup 1.0000x reference)
#include <cuda_runtime.h>
#include <cuda_bf16.h>
#include <cstdint>

// ModalConditionedRPE, GB300 sm_103a.
//
// out[i,j] = b2 + sum_h relu(P[i,h] + Q[j,h]) * W2[h]
//   P[i,h] = x_i*W1[0,h] + y_i*W1[1,h] + s_mean[i]*W1[34,h] + Cmod[h]
//   Q[j,h] = -x_j*W1[0,h] - y_j*W1[1,h] + s_mean[j]*W1[35,h]
//   Cmod[h] = sum_k me[q,k]*W1[2+k,h] + me[km,k]*W1[18+k,h] + b1[h]
// s_mean: jax.image.resize 80->40 linear WITH antialias (4-tap triangle,
// edge-renormalized), mean over batch of 4.

#define NPIX 1600
#define HDIM 64
#define PAD  66   // smem row stride in floats (bank-conflict-free for strided j)

typedef unsigned long long u64;
union F2u { u64 u; float2 f; };

__device__ __forceinline__ u64 add2(u64 a, u64 b) {
    u64 r; asm("add.rn.f32x2 %0, %1, %2;" : "=l"(r) : "l"(a), "l"(b)); return r;
}
__device__ __forceinline__ u64 fma2(u64 a, u64 b, u64 c) {
    u64 r; asm("fma.rn.f32x2 %0, %1, %2, %3;" : "=l"(r) : "l"(a), "l"(b), "l"(c)); return r;
}

__device__ float g_P[NPIX * HDIM];
__device__ float g_Q[NPIX * HDIM];

// 4-tap antialiased triangle weights for 80->40 (matches jax.image.resize
// 'linear', antialias=True, half-pixel centers). sample = 2o + 0.5,
// taps at 2o-1..2o+2, raw weights {.25,.75,.75,.25}, invalid taps zeroed,
// then normalized to sum 1.
__device__ __forceinline__ void resize_taps(int o, float* w, int& t0) {
    t0 = 2 * o - 1;
    const float raw0 = 0.25f, raw1 = 0.75f;
    float ww[4] = { raw0, raw1, raw1, raw0 };
    float s = 0.f;
#pragma unroll
    for (int k = 0; k < 4; k++) {
        int ii = t0 + k;
        if (ii < 0 || ii >= 80) ww[k] = 0.f;
        s += ww[k];
    }
    float inv = 1.f / s;
#pragma unroll
    for (int k = 0; k < 4; k++) w[k] = ww[k] * inv;
}

// One block = 16 output pixels. Computes s_mean for those pixels, Cmod (shared
// across the whole problem, recomputed per block -- trivial), then P/Q rows.
__global__ __launch_bounds__(256) void precompute_kernel(
    const float* __restrict__ smap,   // (4,1,80,80)
    const float* __restrict__ me,     // (3,16)
    const float* __restrict__ W1,     // (36,64)
    const float* __restrict__ b1,     // (64)
    const int*   __restrict__ qmod,
    const int*   __restrict__ kmod)
{
    __shared__ float sm[16];
    __shared__ float cm[HDIM];
    const int t  = threadIdx.x;
    const int i0 = blockIdx.x * 16;

    if (t < 16) {
        int i  = i0 + t;
        int iy = i / 40, ix = i % 40;
        float wy[4], wx[4]; int ty0, tx0;
        resize_taps(iy, wy, ty0);
        resize_taps(ix, wx, tx0);
        float s = 0.f;
#pragma unroll
        for (int b = 0; b < 4; b++) {
            const float* base = smap + b * 6400;
#pragma unroll
            for (int a = 0; a < 4; a++) {
                int yy = ty0 + a;
                if (wy[a] == 0.f) continue;
                float rowacc = 0.f;
#pragma unroll
                for (int c = 0; c < 4; c++) {
                    int xx = tx0 + c;
                    if (wx[c] == 0.f) continue;
                    rowacc += wx[c] * base[yy * 80 + xx];
                }
                s += wy[a] * rowacc;
            }
        }
        sm[t] = s * 0.25f;
    } else if (t >= 64 && t < 128) {
        int h = t - 64;
        int q = qmod[0], km = kmod[0];
        float c = b1[h];
#pragma unroll
        for (int kk = 0; kk < 16; kk++) {
            c += me[q  * 16 + kk] * W1[(2  + kk) * HDIM + h];
            c += me[km * 16 + kk] * W1[(18 + kk) * HDIM + h];
        }
        cm[h] = c;
    }
    __syncthreads();

    // 16 pixels x 64 h = 1024 (i,h) pairs; 256 threads -> 4 each.
    for (int p = t; p < 16 * HDIM; p += 256) {
        int li = p >> 6, h = p & 63;
        int i  = i0 + li;
        float x = -0.5f + (float)(i % 40) * (1.0f / 39.0f);
        float y = -0.5f + (float)(i / 40) * (1.0f / 39.0f);
        float w0  = W1[h];
        float w1  = W1[HDIM + h];
        float wsi = W1[34 * HDIM + h];
        float wsj = W1[35 * HDIM + h];
        float sv  = sm[li];
        g_P[i * HDIM + h] =  x * w0 + y * w1 + sv * wsi + cm[h];
        g_Q[i * HDIM + h] = -x * w0 - y * w1 + sv * wsj;
    }
}

// Main kernel: 64x64 output tile per block, 4x4 per thread (16x16 threads),
// h-loop packed f32x2 (FADD2 / FFMA2 via PTX), relu via scalar FMNMX on the
// ALU pipe. Conflict-free smem via row stride 66.
__global__ __launch_bounds__(256) void rpe_main_kernel(
    const float* __restrict__ W2,   // (64)
    const float* __restrict__ b2,   // (1)
    float*       __restrict__ out)  // (1600,1600)
{
    __shared__ __align__(16) float Ps[64 * PAD];
    __shared__ __align__(16) float Qs[64 * PAD];
    __shared__ __align__(16) float w2s[HDIM];

    const int t  = threadIdx.x;
    const int bi = blockIdx.y * 64;
    const int bj = blockIdx.x * 64;

    // Tile fill: 64 rows x 32 float2 per tile; 256 threads -> 8 float2 each.
#pragma unroll
    for (int k = t; k < 64 * 32; k += 256) {
        int r = k >> 5, c = k & 31;
        float2 vp = *(const float2*)&g_P[(bi + r) * HDIM + 2 * c];
        float2 vq = *(const float2*)&g_Q[(bj + r) * HDIM + 2 * c];
        *(float2*)&Ps[r * PAD + 2 * c] = vp;
        *(float2*)&Qs[r * PAD + 2 * c] = vq;
    }
    if (t < HDIM) w2s[t] = W2[t];
    __syncthreads();

    const int tx = t & 15;   // j group (strided by 16)
    const int ty = t >> 4;   // i group (strided by 16)

    u64 acc[4][4];
#pragma unroll
    for (int r = 0; r < 4; r++)
#pragma unroll
        for (int c = 0; c < 4; c++) acc[r][c] = 0ull;  // packed {+0.f,+0.f}

#pragma unroll 8
    for (int hp = 0; hp < 32; hp++) {
        u64 w2p = *(const u64*)&w2s[2 * hp];
        u64 a[4], b[4];
#pragma unroll
        for (int r = 0; r < 4; r++)
            a[r] = *(const u64*)&Ps[(ty + 16 * r) * PAD + 2 * hp];
#pragma unroll
        for (int c = 0; c < 4; c++)
            b[c] = *(const u64*)&Qs[(tx + 16 * c) * PAD + 2 * hp];

#pragma unroll
        for (int r = 0; r < 4; r++) {
#pragma unroll
            for (int c = 0; c < 4; c++) {
                F2u u;
                u.u = add2(a[r], b[c]);          // FADD2 (fma pipe)
                u.f.x = fmaxf(u.f.x, 0.0f);      // FMNMX (alu pipe)
                u.f.y = fmaxf(u.f.y, 0.0f);
                acc[r][c] = fma2(u.u, w2p, acc[r][c]);  // FFMA2 (fma pipe)
            }
        }
    }

    const float bb = b2[0];
#pragma unroll
    for (int r = 0; r < 4; r++) {
        int gi = bi + ty + 16 * r;
#pragma unroll
        for (int c = 0; c < 4; c++) {
            int gj = bj + tx + 16 * c;
            F2u v; v.u = acc[r][c];
            out[gi * NPIX + gj] = v.f.x + v.f.y + bb;
        }
    }
}

// metadata order: h, w, q_mod, k_mod, structure_map, mod_embed, W1, b1, W2, b2
extern "C" void kernel_launch(void* const* d_in, const int* in_sizes, int n_in,
                              void* d_out, int out_size)
{
    const int*   qmod = (const int*)d_in[2];
    const int*   kmod = (const int*)d_in[3];
    const float* smap = (const float*)d_in[4];
    const float* me   = (const float*)d_in[5];
    const float* W1   = (const float*)d_in[6];
    const float* b1   = (const float*)d_in[7];
    const float* W2   = (const float*)d_in[8];
    const float* b2   = (const float*)d_in[9];
    float* out = (float*)d_out;

    precompute_kernel<<<100, 256>>>(smap, me, W1, b1, qmod, kmod);
    rpe_main_kernel<<<dim3(25, 25), 256>>>(W2, b2, out);
}